// round 4
// baseline (speedup 1.0000x reference)
#include <cuda_runtime.h>

#define N_NODES 50000
#define N_EDGES 800000
#define D 64
#define TR 64            // dst rows per layer block

typedef unsigned long long ull;

// Scratch (__device__ globals: zero-initialized at load; every kernel restores
// its preconditions so the captured graph replays deterministically)
__device__ int   g_cnt[N_NODES];       // degree counters (zero before each count)
__device__ int   g_off[N_NODES];       // CSR exclusive offsets
__device__ int   g_cur[N_NODES];       // fill cursors (rebuilt by scan each call)
__device__ int   g_num[N_NODES];       // degree snapshot
__device__ float g_inv[N_NODES];       // 1/(deg+1)
__device__ int   g_esrc[N_EDGES];      // CSR column (src) indices
__device__ float g_h1[(size_t)N_NODES * D];
__device__ float g_h2[(size_t)N_NODES * D];

// packed f32x2 fma: d = a*b + d on (lo,hi) pairs (FFMA2, rt_SMSP=1)
__device__ __forceinline__ void ffma2(ull& d, ull a, ull b) {
    asm("fma.rn.f32x2 %0, %1, %2, %0;" : "+l"(d) : "l"(a), "l"(b));
}

// ---------------------------------------------------------------------------
// 1) count in-degrees (int atomics; g_cnt zeroed by scan_kernel each call)
__global__ void count_kernel(const int* __restrict__ dst) {
    int e = blockIdx.x * blockDim.x + threadIdx.x;
    if (e < N_EDGES) atomicAdd(&g_cnt[dst[e]], 1);
}

// 2) one-block exclusive scan over 50k degrees; writes offsets, cursors, deg
//    snapshot, inv normalizer; re-zeros g_cnt for the next replay.
__global__ void __launch_bounds__(1024) scan_kernel() {
    __shared__ int ps[1024];
    const int CH = (N_NODES + 1023) / 1024;   // 49
    int t = threadIdx.x;
    int base = t * CH;

    int s = 0;
    for (int i = 0; i < CH; i++) {
        int n = base + i;
        if (n < N_NODES) s += g_cnt[n];
    }
    ps[t] = s;
    __syncthreads();
    for (int off = 1; off < 1024; off <<= 1) {
        int v = (t >= off) ? ps[t - off] : 0;
        __syncthreads();
        ps[t] += v;
        __syncthreads();
    }
    int run = (t == 0) ? 0 : ps[t - 1];
    for (int i = 0; i < CH; i++) {
        int n = base + i;
        if (n < N_NODES) {
            int c = g_cnt[n];
            g_off[n] = run;
            g_cur[n] = run;
            g_num[n] = c;
            g_inv[n] = 1.0f / (float)(c + 1);
            g_cnt[n] = 0;            // ready for next replay
            run += c;
        }
    }
}

// 3) bucket-fill CSR column indices
__global__ void fill_kernel(const int* __restrict__ src,
                            const int* __restrict__ dst) {
    int e = blockIdx.x * blockDim.x + threadIdx.x;
    if (e < N_EDGES) {
        int pos = atomicAdd(&g_cur[dst[e]], 1);
        g_esrc[pos] = src[e];
    }
}

// ---------------------------------------------------------------------------
// Fused layer: per dst row, gather-sum neighbor rows from CSR (no atomics),
// add self, normalize into smem, then FFMA2 register-blocked GEMM + bias(+relu).
// Warp owns 8 rows; lane l covers feature dims {2l, 2l+1} via float2 (one
// LDG.64 per edge per warp = the full 256B row).
template <bool RELU>
__global__ void __launch_bounds__(256) layer_kernel(
        const float* __restrict__ h,
        const float* __restrict__ W,
        const float* __restrict__ b,
        float* __restrict__ out) {
    __shared__ float2 Wq[D * 33];        // Wq[c*33+k2] = (W[2k2][c], W[2k2+1][c])
    __shared__ float vsm[TR * D];
    __shared__ float bs[D];

    int tid = threadIdx.x;
    int rowBase = blockIdx.x * TR;

    float* Wqf = reinterpret_cast<float*>(Wq);
    for (int i = tid; i < D * D; i += 256) {
        int k = i >> 6, c = i & 63;
        Wqf[c * 66 + k] = W[i];
    }
    if (tid < D) bs[tid] = b[tid];

    int warp = tid >> 5;
    int lane = tid & 31;
    int r0 = warp * 8;

    // ---- gather + normalize into vsm ----
    const float2* h2p = reinterpret_cast<const float2*>(h);
#pragma unroll 1
    for (int r = 0; r < 8; r++) {
        int n = rowBase + r0 + r;
        if (n >= N_NODES) break;
        int beg = g_off[n];
        int num = g_num[n];
        float2 acc = __ldg(h2p + (size_t)n * 32 + lane);   // self row
        int j = beg, end = beg + num;
        for (; j + 4 <= end; j += 4) {
            int s0 = __ldg(g_esrc + j);
            int s1 = __ldg(g_esrc + j + 1);
            int s2 = __ldg(g_esrc + j + 2);
            int s3 = __ldg(g_esrc + j + 3);
            float2 a0 = __ldg(h2p + (size_t)s0 * 32 + lane);
            float2 a1 = __ldg(h2p + (size_t)s1 * 32 + lane);
            float2 a2 = __ldg(h2p + (size_t)s2 * 32 + lane);
            float2 a3 = __ldg(h2p + (size_t)s3 * 32 + lane);
            acc.x += a0.x + a1.x + a2.x + a3.x;
            acc.y += a0.y + a1.y + a2.y + a3.y;
        }
        for (; j < end; j++) {
            int s0 = __ldg(g_esrc + j);
            float2 a0 = __ldg(h2p + (size_t)s0 * 32 + lane);
            acc.x += a0.x;
            acc.y += a0.y;
        }
        float iv = g_inv[n];
        acc.x *= iv;
        acc.y *= iv;
        *reinterpret_cast<float2*>(vsm + (r0 + r) * D + 2 * lane) = acc;
    }
    __syncthreads();

    // ---- FFMA2 GEMM: out[rows, :] = vsm @ W + b ----
    ull acc_a[8], acc_b[8];
#pragma unroll
    for (int r = 0; r < 8; r++) { acc_a[r] = 0ull; acc_b[r] = 0ull; }

    const ull* Wa = reinterpret_cast<const ull*>(Wq) + lane * 33;
    const ull* Wb = reinterpret_cast<const ull*>(Wq) + (lane + 32) * 33;
    const ull* vbase = reinterpret_cast<const ull*>(vsm) + r0 * (D / 2);

#pragma unroll
    for (int k2 = 0; k2 < D / 2; k2++) {
        ull wa = Wa[k2];
        ull wb = Wb[k2];
#pragma unroll
        for (int r = 0; r < 8; r++) {
            ull vp = vbase[r * (D / 2) + k2];
            ffma2(acc_a[r], vp, wa);
            ffma2(acc_b[r], vp, wb);
        }
    }

    float bias0 = bs[lane], bias1 = bs[lane + 32];
#pragma unroll
    for (int r = 0; r < 8; r++) {
        int row = rowBase + r0 + r;
        if (row < N_NODES) {
            float2 pa = *reinterpret_cast<float2*>(&acc_a[r]);
            float2 pb = *reinterpret_cast<float2*>(&acc_b[r]);
            float o0 = pa.x + pa.y + bias0;
            float o1 = pb.x + pb.y + bias1;
            if (RELU) { o0 = fmaxf(o0, 0.f); o1 = fmaxf(o1, 0.f); }
            out[(size_t)row * D + lane]      = o0;
            out[(size_t)row * D + lane + 32] = o1;
        }
    }
}

// ---------------------------------------------------------------------------
extern "C" void kernel_launch(void* const* d_in, const int* in_sizes, int n_in,
                              void* d_out, int out_size) {
    const float* x   = (const float*)d_in[0];
    const int*   src = (const int*)  d_in[1];
    const int*   dst = (const int*)  d_in[2];
    const float* W0  = (const float*)d_in[3];
    const float* b0  = (const float*)d_in[4];
    const float* W1  = (const float*)d_in[5];
    const float* b1  = (const float*)d_in[6];
    const float* W2  = (const float*)d_in[7];
    const float* b2  = (const float*)d_in[8];
    float* out = (float*)d_out;

    float* h1;  cudaGetSymbolAddress((void**)&h1, g_h1);
    float* h2;  cudaGetSymbolAddress((void**)&h2, g_h2);

    const int edge_grid  = (N_EDGES + 255) / 256;
    const int layer_grid = (N_NODES + TR - 1) / TR;   // 782

    // CSR build (once per call; reused by all 3 layers)
    count_kernel<<<edge_grid, 256>>>(dst);
    scan_kernel<<<1, 1024>>>();
    fill_kernel<<<edge_grid, 256>>>(src, dst);

    layer_kernel<true ><<<layer_grid, 256>>>(x,  W0, b0, h1);
    layer_kernel<true ><<<layer_grid, 256>>>(h1, W1, b1, h2);
    layer_kernel<false><<<layer_grid, 256>>>(h2, W2, b2, out);
}

// round 5
// speedup vs baseline: 1.8790x; 1.8790x over previous
#include <cuda_runtime.h>

#define N_NODES 50000
#define N_EDGES 800000
#define D 64
#define TR 64            // dst rows per layer block
#define SCAN_B 256
#define SCAN_GRID ((N_NODES + SCAN_B - 1) / SCAN_B)   // 196

typedef unsigned long long ull;

// Scratch (__device__ globals: zero-initialized at load; every kernel restores
// its preconditions so the captured graph replays deterministically)
__device__ int   g_cnt[N_NODES];       // degree counters (zeroed each call by scanC)
__device__ int   g_off[N_NODES];       // CSR exclusive offsets
__device__ int   g_cur[N_NODES];       // fill cursors
__device__ int   g_num[N_NODES];       // degree snapshot
__device__ float g_inv[N_NODES];       // 1/(deg+1)
__device__ int   g_btot[SCAN_GRID];    // per-block totals
__device__ int   g_bbase[SCAN_GRID];   // per-block exclusive bases
__device__ int   g_esrc[N_EDGES];      // CSR column (src) indices
__device__ float g_h1[(size_t)N_NODES * D];
__device__ float g_h2[(size_t)N_NODES * D];

// packed f32x2 fma: d = a*b + d on (lo,hi) pairs (FFMA2, rt_SMSP=1)
__device__ __forceinline__ void ffma2(ull& d, ull a, ull b) {
    asm("fma.rn.f32x2 %0, %1, %2, %0;" : "+l"(d) : "l"(a), "l"(b));
}

// ---------------------------------------------------------------------------
// 1) count in-degrees
__global__ void count_kernel(const int* __restrict__ dst) {
    int e = blockIdx.x * blockDim.x + threadIdx.x;
    if (e < N_EDGES) atomicAdd(&g_cnt[dst[e]], 1);
}

// 2a) per-block scan: local exclusive prefix -> g_off, block total -> g_btot,
//     degree snapshot -> g_num
__global__ void __launch_bounds__(SCAN_B) scanA_kernel() {
    __shared__ int ps[SCAN_B];
    int t = threadIdx.x;
    int n = blockIdx.x * SCAN_B + t;
    int c = (n < N_NODES) ? g_cnt[n] : 0;
    ps[t] = c;
    __syncthreads();
#pragma unroll
    for (int off = 1; off < SCAN_B; off <<= 1) {
        int v = (t >= off) ? ps[t - off] : 0;
        __syncthreads();
        ps[t] += v;
        __syncthreads();
    }
    if (n < N_NODES) {
        g_off[n] = ps[t] - c;          // local exclusive
        g_num[n] = c;
    }
    if (t == SCAN_B - 1) g_btot[blockIdx.x] = ps[t];
}

// 2b) scan of block totals (tiny, one block)
__global__ void __launch_bounds__(SCAN_B) scanB_kernel() {
    __shared__ int ps[SCAN_B];
    int t = threadIdx.x;
    int c = (t < SCAN_GRID) ? g_btot[t] : 0;
    ps[t] = c;
    __syncthreads();
#pragma unroll
    for (int off = 1; off < SCAN_B; off <<= 1) {
        int v = (t >= off) ? ps[t - off] : 0;
        __syncthreads();
        ps[t] += v;
        __syncthreads();
    }
    if (t < SCAN_GRID) g_bbase[t] = ps[t] - c;
}

// 2c) finalize: global offsets, cursors, inv; zero counters for next replay
__global__ void __launch_bounds__(SCAN_B) scanC_kernel() {
    int t = threadIdx.x;
    int n = blockIdx.x * SCAN_B + t;
    if (n < N_NODES) {
        int off = g_off[n] + g_bbase[blockIdx.x];
        g_off[n] = off;
        g_cur[n] = off;
        g_inv[n] = 1.0f / (float)(g_num[n] + 1);
        g_cnt[n] = 0;                  // ready for next replay
    }
}

// 3) bucket-fill CSR column indices
__global__ void fill_kernel(const int* __restrict__ src,
                            const int* __restrict__ dst) {
    int e = blockIdx.x * blockDim.x + threadIdx.x;
    if (e < N_EDGES) {
        int pos = atomicAdd(&g_cur[dst[e]], 1);
        g_esrc[pos] = src[e];
    }
}

// ---------------------------------------------------------------------------
// Fused layer: per dst row, gather-sum neighbor rows from CSR (no atomics),
// add self, normalize into smem, then FFMA2 register-blocked GEMM + bias(+relu).
template <bool RELU>
__global__ void __launch_bounds__(256) layer_kernel(
        const float* __restrict__ h,
        const float* __restrict__ W,
        const float* __restrict__ b,
        float* __restrict__ out) {
    __shared__ float2 Wq[D * 33];        // Wq[c*33+k2] = (W[2k2][c], W[2k2+1][c])
    __shared__ float vsm[TR * D];
    __shared__ float bs[D];

    int tid = threadIdx.x;
    int rowBase = blockIdx.x * TR;

    float* Wqf = reinterpret_cast<float*>(Wq);
    for (int i = tid; i < D * D; i += 256) {
        int k = i >> 6, c = i & 63;
        Wqf[c * 66 + k] = W[i];
    }
    if (tid < D) bs[tid] = b[tid];

    int warp = tid >> 5;
    int lane = tid & 31;
    int r0 = warp * 8;

    // ---- gather + normalize into vsm ----
    const float2* h2p = reinterpret_cast<const float2*>(h);
#pragma unroll 1
    for (int r = 0; r < 8; r++) {
        int n = rowBase + r0 + r;
        if (n >= N_NODES) break;
        int beg = __ldg(g_off + n);
        int num = __ldg(g_num + n);
        float2 acc = __ldg(h2p + (size_t)n * 32 + lane);   // self row
        int j = beg, end = beg + num;
        for (; j + 4 <= end; j += 4) {
            int s0 = __ldg(g_esrc + j);
            int s1 = __ldg(g_esrc + j + 1);
            int s2 = __ldg(g_esrc + j + 2);
            int s3 = __ldg(g_esrc + j + 3);
            float2 a0 = __ldg(h2p + (size_t)s0 * 32 + lane);
            float2 a1 = __ldg(h2p + (size_t)s1 * 32 + lane);
            float2 a2 = __ldg(h2p + (size_t)s2 * 32 + lane);
            float2 a3 = __ldg(h2p + (size_t)s3 * 32 + lane);
            acc.x += a0.x + a1.x + a2.x + a3.x;
            acc.y += a0.y + a1.y + a2.y + a3.y;
        }
        for (; j < end; j++) {
            int s0 = __ldg(g_esrc + j);
            float2 a0 = __ldg(h2p + (size_t)s0 * 32 + lane);
            acc.x += a0.x;
            acc.y += a0.y;
        }
        float iv = __ldg(g_inv + n);
        acc.x *= iv;
        acc.y *= iv;
        *reinterpret_cast<float2*>(vsm + (r0 + r) * D + 2 * lane) = acc;
    }
    __syncthreads();

    // ---- FFMA2 GEMM: out[rows, :] = vsm @ W + b ----
    ull acc_a[8], acc_b[8];
#pragma unroll
    for (int r = 0; r < 8; r++) { acc_a[r] = 0ull; acc_b[r] = 0ull; }

    const ull* Wa = reinterpret_cast<const ull*>(Wq) + lane * 33;
    const ull* Wb = reinterpret_cast<const ull*>(Wq) + (lane + 32) * 33;
    const ull* vbase = reinterpret_cast<const ull*>(vsm) + r0 * (D / 2);

#pragma unroll
    for (int k2 = 0; k2 < D / 2; k2++) {
        ull wa = Wa[k2];
        ull wb = Wb[k2];
#pragma unroll
        for (int r = 0; r < 8; r++) {
            ull vp = vbase[r * (D / 2) + k2];
            ffma2(acc_a[r], vp, wa);
            ffma2(acc_b[r], vp, wb);
        }
    }

    float bias0 = bs[lane], bias1 = bs[lane + 32];
#pragma unroll
    for (int r = 0; r < 8; r++) {
        int row = rowBase + r0 + r;
        if (row < N_NODES) {
            float2 pa = *reinterpret_cast<float2*>(&acc_a[r]);
            float2 pb = *reinterpret_cast<float2*>(&acc_b[r]);
            float o0 = pa.x + pa.y + bias0;
            float o1 = pb.x + pb.y + bias1;
            if (RELU) { o0 = fmaxf(o0, 0.f); o1 = fmaxf(o1, 0.f); }
            out[(size_t)row * D + lane]      = o0;
            out[(size_t)row * D + lane + 32] = o1;
        }
    }
}

// ---------------------------------------------------------------------------
extern "C" void kernel_launch(void* const* d_in, const int* in_sizes, int n_in,
                              void* d_out, int out_size) {
    const float* x   = (const float*)d_in[0];
    const int*   src = (const int*)  d_in[1];
    const int*   dst = (const int*)  d_in[2];
    const float* W0  = (const float*)d_in[3];
    const float* b0  = (const float*)d_in[4];
    const float* W1  = (const float*)d_in[5];
    const float* b1  = (const float*)d_in[6];
    const float* W2  = (const float*)d_in[7];
    const float* b2  = (const float*)d_in[8];
    float* out = (float*)d_out;

    float* h1;  cudaGetSymbolAddress((void**)&h1, g_h1);
    float* h2;  cudaGetSymbolAddress((void**)&h2, g_h2);

    const int edge_grid  = (N_EDGES + 255) / 256;
    const int layer_grid = (N_NODES + TR - 1) / TR;   // 782

    // CSR build (full-chip 3-phase scan)
    count_kernel<<<edge_grid, 256>>>(dst);
    scanA_kernel<<<SCAN_GRID, SCAN_B>>>();
    scanB_kernel<<<1, SCAN_B>>>();
    scanC_kernel<<<SCAN_GRID, SCAN_B>>>();
    fill_kernel<<<edge_grid, 256>>>(src, dst);

    layer_kernel<true ><<<layer_grid, 256>>>(x,  W0, b0, h1);
    layer_kernel<true ><<<layer_grid, 256>>>(h1, W1, b1, h2);
    layer_kernel<false><<<layer_grid, 256>>>(h2, W2, b2, out);
}